// round 7
// baseline (speedup 1.0000x reference)
#include <cuda_runtime.h>
#include <cuda_bf16.h>
#include <cuda_fp16.h>

// Problem constants: b=1, h=w=64, s=5, H=W=1024, ps=32, q=8
#define GRID_T   64
#define NTILES   (GRID_T * GRID_T)      // 4096
#define NSTROKE  5
#define IMG      1024
#define PLANE    (IMG * IMG)            // 1048576

// Scratch (allocation-free rule: __device__ globals)
__device__ int    g_cnt[NTILES];
__device__ float4 g_sA[NTILES * NSTROKE];   // (C, S, U0, V0)   [scaled by 25]
__device__ float4 g_sB[NTILES * NSTROKE];   // (W, H, dS, dC)   [scaled by 25]
__device__ float4 g_sC[NTILES * NSTROKE];   // (cr, cg, cb, -)

__device__ __forceinline__ __half2 tanh2_(__half2 x) {
    unsigned r, xi = *reinterpret_cast<unsigned*>(&x);
    asm("tanh.approx.f16x2 %0,%1;" : "=r"(r) : "r"(xi));
    return *reinterpret_cast<__half2*>(&r);
}

// ---------------------------------------------------------------------------
// Kernel 1: per-STROKE preprocessing, order-preserving compaction of dec==1.
// sigmoid(50*(hw-|u|)) = 0.5*(1+tanh(25*(hw-|u|))) -> fold 25 into coeffs.
// ---------------------------------------------------------------------------
__global__ void prep_kernel(const float* __restrict__ param,
                            const int*   __restrict__ decision) {
    int n = blockIdx.x * blockDim.x + threadIdx.x;
    if (n >= NTILES * NSTROKE) return;
    int t = n / NSTROKE;
    int i = n - t * NSTROKE;

    int d[NSTROKE];
    #pragma unroll
    for (int j = 0; j < NSTROKE; j++) d[j] = decision[t * NSTROKE + j];
    if (i == 0) {
        int cnt = 0;
        #pragma unroll
        for (int j = 0; j < NSTROKE; j++) cnt += (d[j] != 0);
        g_cnt[t] = cnt;
    }
    if (d[i] == 0) return;
    int pos = 0;
    #pragma unroll
    for (int j = 0; j < NSTROKE; j++) pos += (j < i) && (d[j] != 0);

    const float* q = param + (size_t)n * 12;
    float p[8];
    #pragma unroll
    for (int k = 0; k < 8; k++)
        p[k] = 1.0f / (1.0f + expf(-q[k]));     // jax.nn.sigmoid

    float x0 = p[0], y0 = p[1];
    float W = 12.5f * fmaxf(p[2], 0.01f);       // 25 * (wd/2)
    float H = 12.5f * fmaxf(p[3], 0.01f);
    float th = p[4] * 3.14159265358979323846f;
    float st, ct;
    sincosf(th, &st, &ct);

    float C  = 25.0f * ct, S = 25.0f * st;
    float U0 = -(x0 * C + y0 * S);
    float V0 =  (x0 * S - y0 * C);

    int o = t * NSTROKE + pos;
    g_sA[o] = make_float4(C, S, U0, V0);
    g_sB[o] = make_float4(W, H, 0.125f * S, 0.125f * C);
    g_sC[o] = make_float4(p[5], p[6], p[7], 0.f);
}

// ---------------------------------------------------------------------------
// Kernel 2: 256-thread block = 2x2 grid of 16x16 padded cells. Warp w (0..3)
// stages cell w warp-synchronously (shfl for pass counts). Render threads are
// warp-pure per cell: tid>>6 = cell, 4 px/thread (rows ty+{0,4,8,12}).
// tanh evaluated as f16x2 (both stroke edges in one MUFU op).
// ---------------------------------------------------------------------------
__global__ void __launch_bounds__(256)
render_kernel(const float* __restrict__ canvas,
              float*       __restrict__ out) {
    __shared__ float4 sA[4][4 * NSTROKE];
    __shared__ float4 sB[4][4 * NSTROKE];
    __shared__ float4 sC[4][4 * NSTROKE];
    __shared__ int    sTot[4];

    const int tid  = threadIdx.x;
    const int lane = tid & 31;
    const int wrp  = tid >> 5;

    // --- staging: warp w (<4) stages cell w ---
    if (wrp < 4) {
        const int a = 2 * blockIdx.y + (wrp >> 1);   // cell row
        const int b = 2 * blockIdx.x + (wrp & 1);    // cell col
        const int PR[4] = {0, 1, 1, 0};
        const int PC[4] = {0, 1, 0, 1};

        // lanes 0..3: per-pass tile + count
        int cntv = 0;
        {
            int p = lane & 3;
            int r = (((a - 1) & 1) == PR[p]) ? (a - 1) : a;
            int c = (((b - 1) & 1) == PC[p]) ? (b - 1) : b;
            if ((unsigned)r < 64u && (unsigned)c < 64u && lane < 4)
                cntv = g_cnt[r * GRID_T + c];
        }
        int cnt0 = __shfl_sync(0xffffffffu, cntv, 0);
        int cnt1 = __shfl_sync(0xffffffffu, cntv, 1);
        int cnt2 = __shfl_sync(0xffffffffu, cntv, 2);
        int cnt3 = __shfl_sync(0xffffffffu, cntv, 3);
        if (lane == 0) sTot[wrp] = cnt0 + cnt1 + cnt2 + cnt3;

        if (lane < 4 * NSTROKE) {
            int p = lane / NSTROKE, i = lane - p * NSTROKE;
            int cp   = (p == 0) ? cnt0 : (p == 1) ? cnt1 : (p == 2) ? cnt2 : cnt3;
            int base = ((p > 0) ? cnt0 : 0) + ((p > 1) ? cnt1 : 0) + ((p > 2) ? cnt2 : 0);
            if (i < cp) {
                int r = (((a - 1) & 1) == PR[p]) ? (a - 1) : a;
                int c = (((b - 1) & 1) == PC[p]) ? (b - 1) : b;
                int o = (r * GRID_T + c) * NSTROKE + i;
                float4 A = g_sA[o];
                float ox = ((float)(16 * (b - c)) + 0.5f) * 0.03125f;
                float oy = ((float)(16 * (a - r)) + 0.5f) * 0.03125f;
                float U0p = fmaf(ox, A.x, fmaf(oy, A.y, A.z));
                float V0p = fmaf(oy, A.x, fmaf(-ox, A.y, A.w));
                int e = base + i;
                sA[wrp][e] = make_float4(A.x, A.y, U0p, V0p);
                sB[wrp][e] = g_sB[o];
                sC[wrp][e] = g_sC[o];
            }
        }
    }
    __syncthreads();

    // --- render: cell = tid>>6 (warp-pure), 4 px/thread ---
    const int cell = tid >> 6;
    const int t6   = tid & 63;
    const int tx   = t6 & 15;
    const int ty   = t6 >> 4;            // 0..3
    const int a    = 2 * blockIdx.y + (cell >> 1);
    const int b    = 2 * blockIdx.x + (cell & 1);

    const int x  = 16 * b + tx - 8;      // q = 8
    const int y0 = 16 * a + ty - 8;
    const bool vx = (unsigned)x < (unsigned)IMG;

    float r[4], g[4], bl[4];
    int   idx[4];
    bool  vv[4];
    #pragma unroll
    for (int k = 0; k < 4; k++) {
        int y = y0 + 4 * k;
        idx[k] = y * IMG + x;
        vv[k]  = vx && ((unsigned)y < (unsigned)IMG);
        r[k] = g[k] = bl[k] = 0.f;
        if (vv[k]) {
            r[k]  = canvas[idx[k]];
            g[k]  = canvas[PLANE + idx[k]];
            bl[k] = canvas[2 * PLANE + idx[k]];
        }
    }

    const float gx = (float)tx * 0.03125f;
    const float gy = (float)ty * 0.03125f;
    const int   tot = sTot[cell];
    const __half2 H05 = __half2half2(__float2half(0.5f));

    for (int e = 0; e < tot; e++) {            // order matters: sequential blend
        float4 A  = sA[cell][e];
        float4 B  = sB[cell][e];
        float4 Cc = sC[cell][e];

        float u = fmaf(gx, A.x, fmaf(gy, A.y, A.z));
        float v = fmaf(gy, A.x, fmaf(-gx, A.y, A.w));

        #pragma unroll
        for (int k = 0; k < 4; k++) {
            float z1 = B.x - fabsf(u);
            float z2 = B.y - fabsf(v);
            __half2 th = tanh2_(__floats2half2_rn(z1, z2));
            __half2 hh = __hfma2(th, H05, H05);
            float al = __low2float(hh) * __high2float(hh);
            r[k]  = fmaf(al, Cc.x - r[k],  r[k]);
            g[k]  = fmaf(al, Cc.y - g[k],  g[k]);
            bl[k] = fmaf(al, Cc.z - bl[k], bl[k]);
            u += B.z;                           // +4 rows: du = 0.125*S
            v += B.w;                           //          dv = 0.125*C
        }
    }

    #pragma unroll
    for (int k = 0; k < 4; k++) {
        if (vv[k]) {
            out[idx[k]]             = r[k];
            out[PLANE + idx[k]]     = g[k];
            out[2 * PLANE + idx[k]] = bl[k];
        }
    }
}

// ---------------------------------------------------------------------------
extern "C" void kernel_launch(void* const* d_in, const int* in_sizes, int n_in,
                              void* d_out, int out_size) {
    const float* param    = (const float*)d_in[0];   // (1,64,64,5,12) f32
    const int*   decision = (const int*)  d_in[1];   // (1,64,64,5)    i32
    const float* canvas   = (const float*)d_in[2];   // (1,3,1024,1024) f32
    float*       out      = (float*)d_out;           // (1,3,1024,1024) f32

    prep_kernel<<<(NTILES * NSTROKE + 255) / 256, 256>>>(param, decision);

    dim3 bs(256);            // 4 cells per block, 4 px/thread
    dim3 gs(33, 33);         // 66x66 cells (rows/cols 65 auto-invalid)
    render_kernel<<<gs, bs>>>(canvas, out);
}

// round 8
// speedup vs baseline: 1.1515x; 1.1515x over previous
#include <cuda_runtime.h>
#include <cuda_bf16.h>

// Problem constants: b=1, h=w=64, s=5, H=W=1024, ps=32, q=8
#define GRID_T   64
#define NTILES   (GRID_T * GRID_T)      // 4096
#define NSTROKE  5
#define IMG      1024
#define PLANE    (IMG * IMG)            // 1048576

// Scratch (allocation-free rule: __device__ globals)
__device__ int    g_cnt[NTILES];
__device__ float4 g_sA[NTILES * NSTROKE];   // (C, S, U0, V0)   [scaled by 25]
__device__ float4 g_sB[NTILES * NSTROKE];   // (W, H, dS, dC)   [scaled by 25]
__device__ float4 g_sC[NTILES * NSTROKE];   // (cr, cg, cb, -)

__device__ __forceinline__ float tanh_(float x) {
    float r; asm("tanh.approx.f32 %0,%1;" : "=f"(r) : "f"(x)); return r;
}

// ---------------------------------------------------------------------------
// Kernel 1: per-STROKE preprocessing, order-preserving compaction of dec==1.
// sigmoid(50*(hw-|u|)) = 0.5*(1+tanh(25*(hw-|u|))) -> fold 25 into coeffs.
// Fast-intrinsic sigmoid/sincos (~1e-6 accuracy, fine vs 1e-3 threshold).
// ---------------------------------------------------------------------------
__global__ void prep_kernel(const float* __restrict__ param,
                            const int*   __restrict__ decision) {
    int n = blockIdx.x * blockDim.x + threadIdx.x;
    if (n >= NTILES * NSTROKE) return;
    int t = n / NSTROKE;
    int i = n - t * NSTROKE;

    int d[NSTROKE];
    #pragma unroll
    for (int j = 0; j < NSTROKE; j++) d[j] = decision[t * NSTROKE + j];
    if (i == 0) {
        int cnt = 0;
        #pragma unroll
        for (int j = 0; j < NSTROKE; j++) cnt += (d[j] != 0);
        g_cnt[t] = cnt;
    }
    if (d[i] == 0) return;
    int pos = 0;
    #pragma unroll
    for (int j = 0; j < NSTROKE; j++) pos += (j < i) && (d[j] != 0);

    const float* q = param + (size_t)n * 12;
    float p[8];
    #pragma unroll
    for (int k = 0; k < 8; k++)
        p[k] = __fdividef(1.0f, 1.0f + __expf(-q[k]));   // jax.nn.sigmoid

    float x0 = p[0], y0 = p[1];
    float W = 12.5f * fmaxf(p[2], 0.01f);       // 25 * (wd/2)
    float H = 12.5f * fmaxf(p[3], 0.01f);
    float th = p[4] * 3.14159265358979323846f;
    float st, ct;
    __sincosf(th, &st, &ct);

    float C  = 25.0f * ct, S = 25.0f * st;
    float U0 = -(x0 * C + y0 * S);
    float V0 =  (x0 * S - y0 * C);

    int o = t * NSTROKE + pos;
    g_sA[o] = make_float4(C, S, U0, V0);
    g_sB[o] = make_float4(W, H, 0.125f * S, 0.125f * C);
    g_sC[o] = make_float4(p[5], p[6], p[7], 0.f);
}

// ---------------------------------------------------------------------------
// Kernel 2: block = one 16x16 padded-aligned cell, 64 threads (16x4),
// 4 pixels/thread (rows ty, ty+4, ty+8, ty+12).
// FRONT-TO-BACK blend: entries staged in REVERSED blend order; per pixel
//   acc += color * (alpha*T);  T -= alpha*T;   final = acc + canvas*T.
// Canvas loads happen AFTER the stroke loop (DRAM latency hidden by compute).
// ---------------------------------------------------------------------------
__global__ void __launch_bounds__(64)
render_kernel(const float* __restrict__ canvas,
              float*       __restrict__ out) {
    __shared__ float4 sA[4 * NSTROKE];
    __shared__ float4 sB[4 * NSTROKE];
    __shared__ float4 sC[4 * NSTROKE];
    __shared__ int    sCnt[4];
    __shared__ int    sTileB[4];
    __shared__ float  sOX[4], sOY[4];

    const int a = blockIdx.y;            // padded cell row: Y in [16a, 16a+16)
    const int b = blockIdx.x;
    const int tx  = threadIdx.x;         // 0..15
    const int ty  = threadIdx.y;         // 0..3
    const int tid = ty * 16 + tx;

    // --- stage A: per-pass tile resolution ---
    if (tid < 4) {
        const int PR[4] = {0, 1, 1, 0};
        const int PC[4] = {0, 1, 0, 1};
        int r = (((a - 1) & 1) == PR[tid]) ? (a - 1) : a;
        int c = (((b - 1) & 1) == PC[tid]) ? (b - 1) : b;
        bool valid = ((unsigned)r < 64u) && ((unsigned)c < 64u);
        sTileB[tid] = (r * GRID_T + c) * NSTROKE;
        sCnt[tid]   = valid ? g_cnt[r * GRID_T + c] : 0;
        sOX[tid]    = ((float)(16 * (b - c)) + 0.5f) * 0.03125f;
        sOY[tid]    = ((float)(16 * (a - r)) + 0.5f) * 0.03125f;
    }
    __syncthreads();

    // --- stage B: copy entries in REVERSED pass-major blend order, folding
    // the per-pass offsets into U0/V0 ---
    if (tid < 4 * NSTROKE) {
        int p = tid / NSTROKE, i = tid - p * NSTROKE;
        if (i < sCnt[p]) {
            int base = 0;
            if (p > 0) base += sCnt[0];
            if (p > 1) base += sCnt[1];
            if (p > 2) base += sCnt[2];
            int tot = sCnt[0] + sCnt[1] + sCnt[2] + sCnt[3];
            int o = sTileB[p] + i;
            float4 A  = g_sA[o];
            float ox = sOX[p], oy = sOY[p];
            float U0p = fmaf(ox, A.x, fmaf(oy, A.y, A.z));
            float V0p = fmaf(oy, A.x, fmaf(-ox, A.y, A.w));
            int e = tot - 1 - (base + i);        // reversed position
            sA[e] = make_float4(A.x, A.y, U0p, V0p);
            sB[e] = g_sB[o];
            sC[e] = g_sC[o];
        }
    }
    __syncthreads();

    const int tot = sCnt[0] + sCnt[1] + sCnt[2] + sCnt[3];

    // --- four pixels per thread: rows y0 + {0,4,8,12} ---
    const int x  = 16 * b + tx - 8;      // q = 8
    const int y0 = 16 * a + ty - 8;
    const bool vx = (unsigned)x < (unsigned)IMG;

    const float gx = (float)tx * 0.03125f;
    const float gy = (float)ty * 0.03125f;

    float aR[4] = {0.f, 0.f, 0.f, 0.f};
    float aG[4] = {0.f, 0.f, 0.f, 0.f};
    float aB[4] = {0.f, 0.f, 0.f, 0.f};
    float T[4]  = {1.f, 1.f, 1.f, 1.f};

    for (int e = 0; e < tot; e++) {            // reversed order = front-to-back
        float4 A  = sA[e];
        float4 B  = sB[e];
        float4 Cc = sC[e];

        float u = fmaf(gx, A.x, fmaf(gy, A.y, A.z));
        float v = fmaf(gy, A.x, fmaf(-gx, A.y, A.w));

        #pragma unroll
        for (int k = 0; k < 4; k++) {
            float t1 = tanh_(B.x - fabsf(u));
            float t2 = tanh_(B.y - fabsf(v));
            float h1 = fmaf(t1, 0.5f, 0.5f);
            float h2 = fmaf(t2, 0.5f, 0.5f);
            float aT = h1 * h2 * T[k];          // alpha * transmittance
            aR[k] = fmaf(aT, Cc.x, aR[k]);
            aG[k] = fmaf(aT, Cc.y, aG[k]);
            aB[k] = fmaf(aT, Cc.z, aB[k]);
            T[k] -= aT;
            u += B.z;                           // +4 rows: du = 0.125*S
            v += B.w;                           //          dv = 0.125*C
        }
    }

    // --- late canvas read + composite ---
    #pragma unroll
    for (int k = 0; k < 4; k++) {
        int y = y0 + 4 * k;
        if (vx && ((unsigned)y < (unsigned)IMG)) {
            int idx = y * IMG + x;
            out[idx]             = fmaf(canvas[idx],             T[k], aR[k]);
            out[PLANE + idx]     = fmaf(canvas[PLANE + idx],     T[k], aG[k]);
            out[2 * PLANE + idx] = fmaf(canvas[2 * PLANE + idx], T[k], aB[k]);
        }
    }
}

// ---------------------------------------------------------------------------
extern "C" void kernel_launch(void* const* d_in, const int* in_sizes, int n_in,
                              void* d_out, int out_size) {
    const float* param    = (const float*)d_in[0];   // (1,64,64,5,12) f32
    const int*   decision = (const int*)  d_in[1];   // (1,64,64,5)    i32
    const float* canvas   = (const float*)d_in[2];   // (1,3,1024,1024) f32
    float*       out      = (float*)d_out;           // (1,3,1024,1024) f32

    prep_kernel<<<(NTILES * NSTROKE + 255) / 256, 256>>>(param, decision);

    dim3 bs(16, 4);          // 64 threads, 4 px/thread
    dim3 gs(65, 65);         // padded 1040x1040 in 16x16 cells
    render_kernel<<<gs, bs>>>(canvas, out);
}